// round 10
// baseline (speedup 1.0000x reference)
#include <cuda_runtime.h>
#include <cuda_bf16.h>
#include <cuda_fp16.h>
#include <cstdint>

#define NN 50000
#define NE 800000
#define NE2 850000   /* NE + NN self loops */
#define NG 64

// ---------------- device scratch (no allocations allowed) ----------------
__device__ __align__(16) __half g_h16[NN * 256]; // per-layer h = x@W  [N, H*C] fp16
__device__ __align__(16) __nv_bfloat16 g_xhi[(size_t)NN * 128]; // activation hi (stride=K)
__device__ __align__(16) __nv_bfloat16 g_xlo[(size_t)NN * 128]; // activation lo
__device__ __align__(16) float g_als[NN * 4];
__device__ __align__(16) float g_ald[NN * 4];
__device__ __align__(16) float g_alpha[NE2 * 4]; // overflow fallback only
__device__ __align__(16) __nv_bfloat16 g_bthi[256 * 128]; // W^T split hi [n][k]
__device__ __align__(16) __nv_bfloat16 g_btlo[256 * 128]; // W^T split lo [n][k]
__device__ int   g_deg[NN];
__device__ int   g_offs[NN + 1];
__device__ int   g_cursor[NN];
__device__ int   g_ssrc[NE2];
__device__ float g_psum[NG * 64];
__device__ float g_pcnt[NG];

// ---------------- CSR build ----------------
__global__ void k_init() {
  int i = blockIdx.x * blockDim.x + threadIdx.x;
  if (i < NN) g_deg[i] = 1;              // self-loop pre-counted
  if (i < NG * 64) g_psum[i] = 0.f;
  if (i < NG) g_pcnt[i] = 0.f;
}

__global__ void k_degree(const int* __restrict__ ei) {
  int e = blockIdx.x * blockDim.x + threadIdx.x;
  if (e < NE) atomicAdd(&g_deg[ei[NE + e]], 1);
}

__global__ void k_scan() {
  __shared__ int sums[1024];
  const int CH = (NN + 1023) / 1024;   // 49
  int t = threadIdx.x;
  int base = t * CH;
  int s = 0;
  for (int i = 0; i < CH; i++) { int idx = base + i; if (idx < NN) s += g_deg[idx]; }
  sums[t] = s;
  __syncthreads();
  for (int off = 1; off < 1024; off <<= 1) {
    int v = (t >= off) ? sums[t - off] : 0;
    __syncthreads();
    sums[t] += v;
    __syncthreads();
  }
  int run = (t == 0) ? 0 : sums[t - 1];
  for (int i = 0; i < CH; i++) {
    int idx = base + i;
    if (idx < NN) { g_offs[idx] = run; g_cursor[idx] = run; run += g_deg[idx]; }
  }
  if (t == 0) g_offs[NN] = sums[1023];
}

__global__ void k_scatter(const int* __restrict__ ei) {
  int e = blockIdx.x * blockDim.x + threadIdx.x;
  if (e >= NE2) return;
  int s, d;
  if (e < NE) { s = ei[e]; d = ei[NE + e]; }
  else        { s = e - NE; d = s; }
  int pos = atomicAdd(&g_cursor[d], 1);
  g_ssrc[pos] = s;
}

// ---------------- x fp32 -> split bf16 hi/lo (layer-1 input) ----------------
__global__ void k_xsplit(const float* __restrict__ x) {
  int i = blockIdx.x * blockDim.x + threadIdx.x;
  if (i >= NN * 128) return;
  float v = x[i];
  __nv_bfloat16 hi = __float2bfloat16(v);
  g_xhi[i] = hi;
  g_xlo[i] = __float2bfloat16(v - __bfloat162float(hi));
}

// ---------------- W split+transpose: W[K][256] fp32 -> g_bthi/lo [256][K] ----
__global__ void k_bsplit(const float* __restrict__ W, int K) {
  int idx = blockIdx.x * blockDim.x + threadIdx.x;
  if (idx >= 256 * K) return;
  int n = idx / K, k = idx - n * K;
  float v = W[k * 256 + n];
  __nv_bfloat16 hi = __float2bfloat16(v);
  __nv_bfloat16 lo = __float2bfloat16(v - __bfloat162float(hi));
  g_bthi[idx] = hi;
  g_btlo[idx] = lo;
}

// ---------------- tensor-core GEMM + fused attention logits ----------------
__device__ __forceinline__ void mma_bf16(float* c, const uint32_t* a, uint32_t b0, uint32_t b1) {
  asm volatile(
      "mma.sync.aligned.m16n8k16.row.col.f32.bf16.bf16.f32 "
      "{%0,%1,%2,%3}, {%4,%5,%6,%7}, {%8,%9}, {%0,%1,%2,%3};\n"
      : "+f"(c[0]), "+f"(c[1]), "+f"(c[2]), "+f"(c[3])
      : "r"(a[0]), "r"(a[1]), "r"(a[2]), "r"(a[3]), "r"(b0), "r"(b1));
}

__device__ __forceinline__ void ldsm4(uint32_t& r0, uint32_t& r1, uint32_t& r2, uint32_t& r3,
                                      uint32_t addr) {
  asm volatile("ldmatrix.sync.aligned.m8n8.x4.shared.b16 {%0,%1,%2,%3}, [%4];"
               : "=r"(r0), "=r"(r1), "=r"(r2), "=r"(r3) : "r"(addr));
}

#define CPA(dst, src, sz) \
  asm volatile("cp.async.cg.shared.global [%0], [%1], 16, %2;" ::"r"(dst), "l"(src), "r"(sz))

#define SSTR 40

__global__ void __launch_bounds__(256, 2)
k_gemm_mma(int K, const float* __restrict__ as_, const float* __restrict__ ad_) {
  __shared__ __nv_bfloat16 sAhi[128 * SSTR];
  __shared__ __nv_bfloat16 sAlo[128 * SSTR];
  __shared__ __nv_bfloat16 sBhi[128 * SSTR];
  __shared__ __nv_bfloat16 sBlo[128 * SSTR];

  const int bm = blockIdx.y * 128;
  const int bn = blockIdx.x * 128;
  const int tid = threadIdx.x;
  const int warp = tid >> 5, lane = tid & 31;
  const int wm = warp >> 1, wn = warp & 1;     // 4x2 warp grid
  const int gid = lane >> 2, tig = lane & 3;

  // ldmatrix lane-address components
  const int lt = lane >> 3, lr = lane & 7;
  const int a_row = (lt & 1) * 8 + lr;
  const int a_col = (lt >> 1) * 8;
  const int b_row = (lt >> 1) * 8 + lr;
  const int b_col = (lt & 1) * 8;

  const uint32_t uAhi = (uint32_t)__cvta_generic_to_shared(sAhi);
  const uint32_t uAlo = (uint32_t)__cvta_generic_to_shared(sAlo);
  const uint32_t uBhi = (uint32_t)__cvta_generic_to_shared(sBhi);
  const uint32_t uBlo = (uint32_t)__cvta_generic_to_shared(sBlo);

  // staging coordinates: row = tid>>2, col16 = (tid&3)*8
  const int st_r0 = tid >> 2, st_c = (tid & 3) * 8;
  const int st_r1 = st_r0 + 64;

  float acc[2][8][4];
#pragma unroll
  for (int i = 0; i < 2; i++)
#pragma unroll
    for (int j = 0; j < 8; j++)
#pragma unroll
      for (int q = 0; q < 4; q++) acc[i][j][q] = 0.f;

  for (int k0 = 0; k0 < K; k0 += 32) {
    // --- stage A chunk [128][32] via cp.async (pre-split bf16 hi/lo in gmem)
    {
      int gr0 = bm + st_r0, gr1 = bm + st_r1;
      int sz0 = (gr0 < NN) ? 16 : 0, sz1 = (gr1 < NN) ? 16 : 0;
      size_t so0 = (size_t)(gr0 < NN ? gr0 : 0) * K + k0 + st_c;
      size_t so1 = (size_t)(gr1 < NN ? gr1 : 0) * K + k0 + st_c;
      uint32_t do0 = (uint32_t)((st_r0 * SSTR + st_c) * 2);
      uint32_t do1 = (uint32_t)((st_r1 * SSTR + st_c) * 2);
      CPA(uAhi + do0, g_xhi + so0, sz0);
      CPA(uAlo + do0, g_xlo + so0, sz0);
      CPA(uAhi + do1, g_xhi + so1, sz1);
      CPA(uAlo + do1, g_xlo + so1, sz1);
      // --- stage B chunk [128][32]
      size_t bo0 = (size_t)(bn + st_r0) * K + k0 + st_c;
      size_t bo1 = (size_t)(bn + st_r1) * K + k0 + st_c;
      CPA(uBhi + do0, g_bthi + bo0, 16);
      CPA(uBlo + do0, g_btlo + bo0, 16);
      CPA(uBhi + do1, g_bthi + bo1, 16);
      CPA(uBlo + do1, g_btlo + bo1, 16);
    }
    asm volatile("cp.async.commit_group;");
    asm volatile("cp.async.wait_group 0;");
    __syncthreads();

#pragma unroll
    for (int ks = 0; ks < 2; ks++) {
      const int kb = ks * 16;
      uint32_t ahi[2][4], alo[2][4];
#pragma unroll
      for (int i = 0; i < 2; i++) {
        uint32_t off = (uint32_t)(((wm * 32 + i * 16 + a_row) * SSTR + kb + a_col) * 2);
        ldsm4(ahi[i][0], ahi[i][1], ahi[i][2], ahi[i][3], uAhi + off);
        ldsm4(alo[i][0], alo[i][1], alo[i][2], alo[i][3], uAlo + off);
      }
#pragma unroll
      for (int jj = 0; jj < 4; jj++) {
        uint32_t off = (uint32_t)(((wn * 64 + jj * 16 + b_row) * SSTR + kb + b_col) * 2);
        uint32_t bh0, bh1, bh2, bh3, bl0, bl1, bl2, bl3;
        ldsm4(bh0, bh1, bh2, bh3, uBhi + off);
        ldsm4(bl0, bl1, bl2, bl3, uBlo + off);
#pragma unroll
        for (int i = 0; i < 2; i++) {
          mma_bf16(acc[i][jj * 2],     ahi[i], bh0, bh1);
          mma_bf16(acc[i][jj * 2],     ahi[i], bl0, bl1);
          mma_bf16(acc[i][jj * 2],     alo[i], bh0, bh1);
          mma_bf16(acc[i][jj * 2 + 1], ahi[i], bh2, bh3);
          mma_bf16(acc[i][jj * 2 + 1], ahi[i], bl2, bl3);
          mma_bf16(acc[i][jj * 2 + 1], alo[i], bh2, bh3);
        }
      }
    }
    __syncthreads();
  }

  // --- epilogue 1: write fp16 h
#pragma unroll
  for (int i = 0; i < 2; i++) {
#pragma unroll
    for (int j = 0; j < 8; j++) {
      int row = bm + wm * 32 + i * 16 + gid;
      int col = bn + wn * 64 + j * 8 + 2 * tig;
      __half2 p01 = __floats2half2_rn(acc[i][j][0], acc[i][j][1]);
      __half2 p23 = __floats2half2_rn(acc[i][j][2], acc[i][j][3]);
      if (row < NN)
        *(__half2*)(g_h16 + (size_t)row * 256 + col) = p01;
      if (row + 8 < NN)
        *(__half2*)(g_h16 + (size_t)(row + 8) * 256 + col) = p23;
    }
  }

  // --- epilogue 2: fused attention logits for head = 2*bn + wn
  {
    const int head = blockIdx.x * 2 + wn;
    float wa[16], wd[16];
#pragma unroll
    for (int j = 0; j < 8; j++) {
      int c = j * 8 + 2 * tig;
      wa[j * 2 + 0] = as_[head * 64 + c];
      wa[j * 2 + 1] = as_[head * 64 + c + 1];
      wd[j * 2 + 0] = ad_[head * 64 + c];
      wd[j * 2 + 1] = ad_[head * 64 + c + 1];
    }
#pragma unroll
    for (int i = 0; i < 2; i++) {
      float s0 = 0.f, s1 = 0.f, d0 = 0.f, d1 = 0.f;
#pragma unroll
      for (int j = 0; j < 8; j++) {
        s0 = fmaf(acc[i][j][0], wa[j * 2], fmaf(acc[i][j][1], wa[j * 2 + 1], s0));
        s1 = fmaf(acc[i][j][2], wa[j * 2], fmaf(acc[i][j][3], wa[j * 2 + 1], s1));
        d0 = fmaf(acc[i][j][0], wd[j * 2], fmaf(acc[i][j][1], wd[j * 2 + 1], d0));
        d1 = fmaf(acc[i][j][2], wd[j * 2], fmaf(acc[i][j][3], wd[j * 2 + 1], d1));
      }
#pragma unroll
      for (int o = 1; o <= 2; o <<= 1) {
        s0 += __shfl_xor_sync(0xffffffffu, s0, o);
        s1 += __shfl_xor_sync(0xffffffffu, s1, o);
        d0 += __shfl_xor_sync(0xffffffffu, d0, o);
        d1 += __shfl_xor_sync(0xffffffffu, d1, o);
      }
      if (tig == 0) {
        int row = bm + wm * 32 + i * 16 + gid;
        if (row < NN)     { g_als[row * 4 + head] = s0; g_ald[row * 4 + head] = d0; }
        if (row + 8 < NN) { g_als[(row + 8) * 4 + head] = s1; g_ald[(row + 8) * 4 + head] = d1; }
      }
    }
  }
}

// ---------------- softmax + aggregation: one warp per dst node ----------------
// Max-shift skipped: logits are O(1) by construction -> exp cannot overflow.
// Per-edge alpha cached in shared memory (gmem fallback for deg > 64).
__device__ __forceinline__ float leaky(float v) { return v >= 0.f ? v : 0.2f * v; }

#define ACAP 64

__global__ void __launch_bounds__(256)
k_agg(const float* __restrict__ bias, float* __restrict__ emb, int final_) {
  __shared__ float4 s_alpha[8][ACAP];
  int warp = (blockIdx.x * blockDim.x + threadIdx.x) >> 5;
  int wip = threadIdx.x >> 5;
  int lane = threadIdx.x & 31;
  if (warp >= NN) return;
  const int n = warp;
  const int beg = g_offs[n], end = g_offs[n + 1];

  const float4 ald = *(const float4*)&g_ald[n * 4];

  float d0 = 0.f, d1 = 0.f, d2 = 0.f, d3 = 0.f;
  for (int e = beg + lane; e < end; e += 32) {
    int s = g_ssrc[e];
    float4 als = *(const float4*)&g_als[s * 4];
    float p0 = __expf(leaky(als.x + ald.x));
    float p1 = __expf(leaky(als.y + ald.y));
    float p2 = __expf(leaky(als.z + ald.z));
    float p3 = __expf(leaky(als.w + ald.w));
    d0 += p0; d1 += p1; d2 += p2; d3 += p3;
    int idx = e - beg;
    float4 pv = make_float4(p0, p1, p2, p3);
    if (idx < ACAP) s_alpha[wip][idx] = pv;
    else            *(float4*)&g_alpha[(size_t)e * 4] = pv;
  }
#pragma unroll
  for (int o = 16; o; o >>= 1) {
    d0 += __shfl_xor_sync(0xffffffffu, d0, o);
    d1 += __shfl_xor_sync(0xffffffffu, d1, o);
    d2 += __shfl_xor_sync(0xffffffffu, d2, o);
    d3 += __shfl_xor_sync(0xffffffffu, d3, o);
  }
  __syncwarp();

  const bool hs = (lane & 16) != 0;
  const float rA = 1.0f / (hs ? d1 : d0);
  const float rB = 1.0f / (hs ? d3 : d2);

  // phase B: warp-serial over edges (unroll 4); lanes cover 256 feats.
  float4 acc0 = make_float4(0.f, 0.f, 0.f, 0.f);
  float4 acc1 = make_float4(0.f, 0.f, 0.f, 0.f);
  const int deg = end - beg;
  int idx = 0;
  for (; idx + 3 < deg; idx += 4) {
    int s[4]; float4 p[4]; uint2 r0[4], r1[4];
#pragma unroll
    for (int j = 0; j < 4; j++) s[j] = g_ssrc[beg + idx + j];
#pragma unroll
    for (int j = 0; j < 4; j++)
      p[j] = (idx + j < ACAP) ? s_alpha[wip][idx + j]
                              : *(const float4*)&g_alpha[(size_t)(beg + idx + j) * 4];
#pragma unroll
    for (int j = 0; j < 4; j++) {
      const uint2* hp = (const uint2*)(g_h16 + (size_t)s[j] * 256);
      r0[j] = __ldg(hp + lane);
      r1[j] = __ldg(hp + 32 + lane);
    }
#pragma unroll
    for (int j = 0; j < 4; j++) {
      float a0 = (hs ? p[j].y : p[j].x) * rA;
      float a1 = (hs ? p[j].w : p[j].z) * rB;
      float2 f;
      f = __half22float2(*(const __half2*)&r0[j].x); acc0.x = fmaf(f.x, a0, acc0.x); acc0.y = fmaf(f.y, a0, acc0.y);
      f = __half22float2(*(const __half2*)&r0[j].y); acc0.z = fmaf(f.x, a0, acc0.z); acc0.w = fmaf(f.y, a0, acc0.w);
      f = __half22float2(*(const __half2*)&r1[j].x); acc1.x = fmaf(f.x, a1, acc1.x); acc1.y = fmaf(f.y, a1, acc1.y);
      f = __half22float2(*(const __half2*)&r1[j].y); acc1.z = fmaf(f.x, a1, acc1.z); acc1.w = fmaf(f.y, a1, acc1.w);
    }
  }
  for (; idx < deg; ++idx) {
    int s = g_ssrc[beg + idx];
    float4 p = (idx < ACAP) ? s_alpha[wip][idx] : *(const float4*)&g_alpha[(size_t)(beg + idx) * 4];
    float a0 = (hs ? p.y : p.x) * rA;
    float a1 = (hs ? p.w : p.z) * rB;
    const uint2* hp = (const uint2*)(g_h16 + (size_t)s * 256);
    uint2 r0 = __ldg(hp + lane);
    uint2 r1 = __ldg(hp + 32 + lane);
    float2 f;
    f = __half22float2(*(const __half2*)&r0.x); acc0.x = fmaf(f.x, a0, acc0.x); acc0.y = fmaf(f.y, a0, acc0.y);
    f = __half22float2(*(const __half2*)&r0.y); acc0.z = fmaf(f.x, a0, acc0.z); acc0.w = fmaf(f.y, a0, acc0.w);
    f = __half22float2(*(const __half2*)&r1.x); acc1.x = fmaf(f.x, a1, acc1.x); acc1.y = fmaf(f.y, a1, acc1.y);
    f = __half22float2(*(const __half2*)&r1.y); acc1.z = fmaf(f.x, a1, acc1.z); acc1.w = fmaf(f.y, a1, acc1.w);
  }

  float4 t;
  t.x = acc0.x + acc1.x; t.y = acc0.y + acc1.y;
  t.z = acc0.z + acc1.z; t.w = acc0.w + acc1.w;
  t.x += __shfl_xor_sync(0xffffffffu, t.x, 16);
  t.y += __shfl_xor_sync(0xffffffffu, t.y, 16);
  t.z += __shfl_xor_sync(0xffffffffu, t.z, 16);
  t.w += __shfl_xor_sync(0xffffffffu, t.w, 16);
  if (lane < 16) {
    const float4 b4 = *(const float4*)(bias + lane * 4);
    float ox = t.x * 0.25f + b4.x;
    float oy = t.y * 0.25f + b4.y;
    float oz = t.z * 0.25f + b4.z;
    float ow = t.w * 0.25f + b4.w;
    if (final_) {
      *(float4*)(emb + (size_t)n * 64 + lane * 4) = make_float4(ox, oy, oz, ow);
    } else {
      ox = fmaxf(ox, 0.f); oy = fmaxf(oy, 0.f);
      oz = fmaxf(oz, 0.f); ow = fmaxf(ow, 0.f);
      // split to bf16 hi/lo for the next GEMM's cp.async staging (stride 64)
      __nv_bfloat16 hx = __float2bfloat16(ox), hy = __float2bfloat16(oy);
      __nv_bfloat16 hz = __float2bfloat16(oz), hw = __float2bfloat16(ow);
      __nv_bfloat16 lx = __float2bfloat16(ox - __bfloat162float(hx));
      __nv_bfloat16 ly = __float2bfloat16(oy - __bfloat162float(hy));
      __nv_bfloat16 lz = __float2bfloat16(oz - __bfloat162float(hz));
      __nv_bfloat16 lw = __float2bfloat16(ow - __bfloat162float(hw));
      uint2 hv, lv;
      *(__nv_bfloat162*)&hv.x = __nv_bfloat162(hx, hy);
      *(__nv_bfloat162*)&hv.y = __nv_bfloat162(hz, hw);
      *(__nv_bfloat162*)&lv.x = __nv_bfloat162(lx, ly);
      *(__nv_bfloat162*)&lv.y = __nv_bfloat162(lz, lw);
      *(uint2*)(g_xhi + (size_t)n * 64 + lane * 4) = hv;
      *(uint2*)(g_xlo + (size_t)n * 64 + lane * 4) = lv;
    }
  }
}

// ---------------- node MLP heads + pooling ----------------
__device__ __forceinline__ float sigmoidf_(float x) { return 1.0f / (1.0f + __expf(-x)); }

__global__ void k_node_mlp(const float* __restrict__ emb, const int* __restrict__ batch,
                           const float* __restrict__ aw1, const float* __restrict__ ab1,
                           const float* __restrict__ aw2, const float* __restrict__ ab2,
                           const float* __restrict__ rw1, const float* __restrict__ rb1,
                           const float* __restrict__ rw2, const float* __restrict__ rb2,
                           const float* __restrict__ cw1, const float* __restrict__ cb1,
                           const float* __restrict__ cw2, const float* __restrict__ cb2,
                           float* __restrict__ anomaly, float* __restrict__ risk,
                           float* __restrict__ resource) {
  int warp = (blockIdx.x * blockDim.x + threadIdx.x) >> 5;
  int lane = threadIdx.x & 31;
  if (warp >= NN) return;
  int n = warp;
  float e0 = emb[(size_t)n * 64 + lane];
  float e1 = emb[(size_t)n * 64 + 32 + lane];

  float ha = ab1[lane], hr = rb1[lane], hc = cb1[lane];
#pragma unroll
  for (int k = 0; k < 32; k++) {
    float ek = __shfl_sync(0xffffffffu, e0, k);
    ha = fmaf(ek, aw1[k * 32 + lane], ha);
    hr = fmaf(ek, rw1[k * 32 + lane], hr);
    hc = fmaf(ek, cw1[k * 32 + lane], hc);
  }
#pragma unroll
  for (int k = 0; k < 32; k++) {
    float ek = __shfl_sync(0xffffffffu, e1, k);
    ha = fmaf(ek, aw1[(k + 32) * 32 + lane], ha);
    hr = fmaf(ek, rw1[(k + 32) * 32 + lane], hr);
    hc = fmaf(ek, cw1[(k + 32) * 32 + lane], hc);
  }
  ha = fmaxf(ha, 0.f); hr = fmaxf(hr, 0.f); hc = fmaxf(hc, 0.f);

  float va = ha * aw2[lane];
  float vr = hr * rw2[lane];
#pragma unroll
  for (int o = 16; o; o >>= 1) {
    va += __shfl_xor_sync(0xffffffffu, va, o);
    vr += __shfl_xor_sync(0xffffffffu, vr, o);
  }
  if (lane == 0) {
    anomaly[n] = sigmoidf_(va + ab2[0]);
    risk[n]    = sigmoidf_(vr + rb2[0]);
  }
#pragma unroll
  for (int o5 = 0; o5 < 5; o5++) {
    float vc = hc * cw2[lane * 5 + o5];
#pragma unroll
    for (int o = 16; o; o >>= 1) vc += __shfl_xor_sync(0xffffffffu, vc, o);
    if (lane == 0) resource[(size_t)n * 5 + o5] = vc + cb2[o5];
  }

  int g = batch[n];
  atomicAdd(&g_psum[g * 64 + lane], e0);
  atomicAdd(&g_psum[g * 64 + 32 + lane], e1);
  if (lane == 0) atomicAdd(&g_pcnt[g], 1.0f);
}

__global__ void k_graph_head(const float* __restrict__ gw1, const float* __restrict__ gb1,
                             const float* __restrict__ gw2, const float* __restrict__ gb2,
                             float* __restrict__ glog) {
  int g = blockIdx.x;
  int lane = threadIdx.x;
  float rc = 1.0f / fmaxf(g_pcnt[g], 1.0f);
  float hid = gb1[lane];
#pragma unroll
  for (int c = 0; c < 64; c++)
    hid = fmaf(g_psum[g * 64 + c] * rc, gw1[c * 32 + lane], hid);
  hid = fmaxf(hid, 0.f);
#pragma unroll
  for (int o4 = 0; o4 < 4; o4++) {
    float v = hid * gw2[lane * 4 + o4];
#pragma unroll
    for (int o = 16; o; o >>= 1) v += __shfl_xor_sync(0xffffffffu, v, o);
    if (lane == 0) glog[g * 4 + o4] = v + gb2[o4];
  }
}

// ---------------- launch ----------------
extern "C" void kernel_launch(void* const* d_in, const int* in_sizes, int n_in,
                              void* d_out, int out_size) {
  const float* x    = (const float*)d_in[0];
  const int*   ei   = (const int*)d_in[1];
  const int*   batch= (const int*)d_in[2];
  const float* W1   = (const float*)d_in[3];
  const float* as1  = (const float*)d_in[4];
  const float* ad1  = (const float*)d_in[5];
  const float* b1   = (const float*)d_in[6];
  const float* W2   = (const float*)d_in[7];
  const float* as2  = (const float*)d_in[8];
  const float* ad2  = (const float*)d_in[9];
  const float* b2   = (const float*)d_in[10];
  const float* W3   = (const float*)d_in[11];
  const float* as3  = (const float*)d_in[12];
  const float* ad3  = (const float*)d_in[13];
  const float* b3   = (const float*)d_in[14];
  const float* aw1  = (const float*)d_in[15];
  const float* ab1  = (const float*)d_in[16];
  const float* aw2  = (const float*)d_in[17];
  const float* ab2  = (const float*)d_in[18];
  const float* rw1  = (const float*)d_in[19];
  const float* rb1  = (const float*)d_in[20];
  const float* rw2  = (const float*)d_in[21];
  const float* rb2  = (const float*)d_in[22];
  const float* cw1  = (const float*)d_in[23];
  const float* cb1  = (const float*)d_in[24];
  const float* cw2  = (const float*)d_in[25];
  const float* cb2  = (const float*)d_in[26];
  const float* gw1  = (const float*)d_in[27];
  const float* gb1  = (const float*)d_in[28];
  const float* gw2  = (const float*)d_in[29];
  const float* gb2  = (const float*)d_in[30];

  float* out      = (float*)d_out;
  float* emb      = out;                        // N*64
  float* anomaly  = out + (size_t)NN * 64;      // N
  float* risk     = anomaly + NN;               // N
  float* resource = risk + NN;                  // N*5
  float* glog     = resource + (size_t)NN * 5;  // G*4

  dim3 gg(2, (NN + 127) / 128);
  int agg_grid = (NN * 32 + 255) / 256;

  k_init<<<(NN + 255) / 256, 256>>>();
  k_degree<<<(NE + 255) / 256, 256>>>(ei);
  k_xsplit<<<(NN * 128 + 255) / 256, 256>>>(x);
  k_bsplit<<<(256 * 128 + 255) / 256, 256>>>(W1, 128);
  k_gemm_mma<<<gg, 256>>>(128, as1, ad1);
  k_scan<<<1, 1024>>>();
  k_scatter<<<(NE2 + 255) / 256, 256>>>(ei);
  k_agg<<<agg_grid, 256>>>(b1, nullptr, 0);

  // layer 2 (K=64)
  k_bsplit<<<(256 * 64 + 255) / 256, 256>>>(W2, 64);
  k_gemm_mma<<<gg, 256>>>(64, as2, ad2);
  k_agg<<<agg_grid, 256>>>(b2, nullptr, 0);
  // layer 3 (K=64)
  k_bsplit<<<(256 * 64 + 255) / 256, 256>>>(W3, 64);
  k_gemm_mma<<<gg, 256>>>(64, as3, ad3);
  k_agg<<<agg_grid, 256>>>(b3, emb, 1);

  // heads
  k_node_mlp<<<agg_grid, 256>>>(emb, batch, aw1, ab1, aw2, ab2,
                                rw1, rb1, rw2, rb2, cw1, cb1, cw2, cb2,
                                anomaly, risk, resource);
  k_graph_head<<<NG, 32>>>(gw1, gb1, gw2, gb2, glog);
}